// round 14
// baseline (speedup 1.0000x reference)
#include <cuda_runtime.h>
#include <math.h>

#define T_LEN 1024
#define NN    1022            /* templates */
#define PAD   1104            /* max smem read index ~1060 */
#define RR    0.2f
#define NTHR  768
#define NWARP (NTHR / 32)
#define NSLOT 12

typedef unsigned long long u64;

__device__ float g_ent[128];
__device__ unsigned int g_barrier;

__device__ __forceinline__ u64 fma2(u64 a, u64 b, u64 c) {
    u64 r;
    asm("fma.rn.f32x2 %0, %1, %2, %3;" : "=l"(r) : "l"(a), "l"(b), "l"(c));
    return r;
}
__device__ __forceinline__ unsigned int lo32(u64 v) { return (unsigned int)v; }
__device__ __forceinline__ unsigned int hi32(u64 v) { return (unsigned int)(v >> 32); }

// Two pairs (lower k first): d2 = fma2(W,-1,A); u2 = fma2(d2,d2,-Rs2);
// insert both sign bits MSB-first.
#define FMA2SH(acc, W, A)                                            \
    do {                                                             \
        u64 _d = fma2((W), NEG1, (A));                               \
        u64 _u = fma2(_d, _d, NRS2);                                 \
        (acc) = __funnelshift_l(lo32(_u), (acc), 1);                 \
        (acc) = __funnelshift_l(hi32(_u), (acc), 1);                 \
    } while (0)

// ---- fused 8-diagonal unit: chunk k0..k0+31 of diagonals dbase..dbase+7
// (dbase ≡ 1 mod 8). Diagonals s+4 reuse the s window stream shifted by one
// ulonglong2, so ONE (A, E, Y) load triple per q-iter serves 32 pairs.
// Aligned ulonglong2 loads: evens from xs, odds from ys (ys[i] = xs[i+1]).
// Bit = sign((a-b)^2 - Rs2), MSB-first; 34 booleans/diagonal (32 + 2 ext). ----
__device__ __forceinline__ void unit8_count(const float* __restrict__ xs,
                                            const float* __restrict__ ys,
                                            int k0, int dbase, int remBase,
                                            float Rs2, u64 NEG1, u64 NRS2,
                                            unsigned int& cm, unsigned int& cm1) {
    const int B = k0 + dbase - 1;                     // ≡ 0 mod 4
    const ulonglong2* __restrict__ Ap = reinterpret_cast<const ulonglong2*>(xs + k0);
    const ulonglong2* __restrict__ Ep = reinterpret_cast<const ulonglong2*>(xs + B);
    const ulonglong2* __restrict__ Yp = reinterpret_cast<const ulonglong2*>(ys + B);
    unsigned int a0 = 0, a1 = 0, a2 = 0, a3 = 0, a4 = 0, a5 = 0, a6 = 0, a7 = 0;
    u64 e1        = Ep[0].y;       // floats (B+2, B+3)
    ulonglong2 E1 = Ep[1];         // (B+4..B+7)
    ulonglong2 Y0 = Yp[0];         // (B+1..B+4)
    ulonglong2 Y1 = Yp[1];         // (B+5..B+8)
    #pragma unroll
    for (int q = 0; q < 8; q++) {
        ulonglong2 A  = Ap[q];     // pairs 4q..4q+3 of the A-stream
        ulonglong2 E2 = Ep[q + 2];
        ulonglong2 Y2 = Yp[q + 2];
        FMA2SH(a0, Y0.x, A.x);  FMA2SH(a0, Y0.y, A.y);   // s=0
        FMA2SH(a1, e1,   A.x);  FMA2SH(a1, E1.x, A.y);   // s=1
        FMA2SH(a2, Y0.y, A.x);  FMA2SH(a2, Y1.x, A.y);   // s=2
        FMA2SH(a3, E1.x, A.x);  FMA2SH(a3, E1.y, A.y);   // s=3
        FMA2SH(a4, Y1.x, A.x);  FMA2SH(a4, Y1.y, A.y);   // s=4
        FMA2SH(a5, E1.y, A.x);  FMA2SH(a5, E2.x, A.y);   // s=5
        FMA2SH(a6, Y1.y, A.x);  FMA2SH(a6, Y2.x, A.y);   // s=6
        FMA2SH(a7, E2.x, A.x);  FMA2SH(a7, E2.y, A.y);   // s=7
        e1 = E1.y; E1 = E2; Y0 = Y1; Y1 = Y2;
    }
    // epilogue: j = 32, 33 per diagonal; then masked neighbor-AND counting
    const float a32 = xs[k0 + 32];
    const float a33 = xs[k0 + 33];
    unsigned int acc[8] = {a0, a1, a2, a3, a4, a5, a6, a7};
    #pragma unroll
    for (int s = 0; s < 8; s++) {
        float W33 = xs[B + 33 + s];
        float W34 = xs[B + 34 + s];
        float d32 = a32 - W33;
        float d33 = a33 - W34;
        float u32 = fmaf(d32, d32, -Rs2);
        float u33 = fmaf(d33, d33, -Rs2);
        unsigned int ext = (__float_as_uint(u32) & 0x80000000u)
                         | ((__float_as_uint(u33) >> 1) & 0x40000000u);
        int rem = remBase - s;
        unsigned int mask = (rem >= 32) ? 0xffffffffu
                          : ((rem <= 0) ? 0u : (0xffffffffu << (32 - rem)));
        unsigned int S1 = __funnelshift_l(ext, acc[s], 1);
        unsigned int S2 = __funnelshift_l(ext, acc[s], 2);
        unsigned int mm = acc[s] & S1 & mask;
        cm  += __popc(mm);
        cm1 += __popc(mm & S2);
    }
}

__global__ __launch_bounds__(NTHR, 1)
void sampen_kernel(const float* __restrict__ pred, const float* __restrict__ tgt,
                   float* __restrict__ out) {
    __shared__ __align__(16) float xs[PAD];
    __shared__ __align__(16) float ys[PAD];     // ys[i] = xs[i+1]
    __shared__ double redA[NWARP], redB[NWARP];
    __shared__ unsigned int redc[NWARP], redc1[NWARP];
    __shared__ float s_thresh2;

    const int s   = blockIdx.x;
    const int tid = threadIdx.x;
    const float* src = (s < 64) ? (pred + (size_t)s * T_LEN)
                                : (tgt  + (size_t)(s - 64) * T_LEN);

    // ---- load raw signal + zero pad ----
    float v0 = src[tid];
    float v1 = (tid + NTHR < T_LEN) ? src[tid + NTHR] : 0.0f;
    xs[tid] = v0;
    if (tid + NTHR < T_LEN) xs[tid + NTHR] = v1;
    for (int i = T_LEN + tid; i < PAD; i += NTHR) xs[i] = 0.0f;

    // ---- std (ddof=1) in double; mean cancels inside |xi-xj|:
    //      squared scaled threshold Rs2 = (R*(std+eps))^2 ----
    double ls  = (double)v0 + (double)v1;
    double ls2 = (double)v0 * (double)v0 + (double)v1 * (double)v1;
    #pragma unroll
    for (int o = 16; o > 0; o >>= 1) {
        ls  += __shfl_down_sync(0xffffffffu, ls,  o);
        ls2 += __shfl_down_sync(0xffffffffu, ls2, o);
    }
    if ((tid & 31) == 0) { redA[tid >> 5] = ls; redB[tid >> 5] = ls2; }
    __syncthreads();
    // build shifted copy (xs fully visible now); overlaps with tid0's reduction
    for (int i = tid; i < PAD - 1; i += NTHR) ys[i] = xs[i + 1];
    if (tid == 0) {
        ys[PAD - 1] = 0.0f;
        double S = 0.0, S2 = 0.0;
        #pragma unroll
        for (int w = 0; w < NWARP; w++) { S += redA[w]; S2 += redB[w]; }
        double var = (S2 - S * S / (double)T_LEN) / (double)(T_LEN - 1);
        double sd  = sqrt(var);
        double rs  = (double)RR * (sd + 1e-8);
        s_thresh2  = (float)(rs * rs);
    }
    __syncthreads();
    const float Rs2 = s_thresh2;
    const u64 NEG1 = 0xBF800000BF800000ull;               // (-1.0f, -1.0f)
    const unsigned int nr = __float_as_uint(-Rs2);
    const u64 NRS2 = (u64)nr | ((u64)nr << 32);           // (-Rs2, -Rs2)

    // ---- upper-triangle counting: fused 8-diagonal chunk units ----
    // Group g covers diagonals 8g+1..8g+8, g in [0,128); overflow diagonals
    // mask to 0. Pair (P, 127-P): exactly 33 units for every P in [0,64).
    // Thread = (P = tid & 63, slot = tid >> 6 in [0,12)); slot owns [g0, g1)
    // of the 33 units ({2,3} per slot); slot is warp-uniform -> uniform trips.
    const int P  = tid & 63;
    const int sg = tid >> 6;           // warp-uniform, 0..11
    const int dA = 8 * P + 1;
    const int LA = NN - dA;            // 1021 - 8P
    const int dB = 1017 - 8 * P;       // partner group 127-P
    const int LB = NN - dB;            // 5 + 8P
    const int CA = (LA + 31) >> 5;
    const int g0 = (sg * 33) / NSLOT;
    const int g1 = ((sg + 1) * 33) / NSLOT;

    unsigned int cm = 0, cm1 = 0;
    for (int j = g0; j < g1; j++) {
        bool inA  = (j < CA);
        int dbase = inA ? dA : dB;
        int c     = inA ? j  : j - CA;
        int Lb    = inA ? LA : LB;
        int k0    = c << 5;
        unit8_count(xs, ys, k0, dbase, Lb - k0, Rs2, NEG1, NRS2, cm, cm1);
    }

    // ---- reduce counts ----
    #pragma unroll
    for (int o = 16; o > 0; o >>= 1) {
        cm  += __shfl_down_sync(0xffffffffu, cm,  o);
        cm1 += __shfl_down_sync(0xffffffffu, cm1, o);
    }
    if ((tid & 31) == 0) { redc[tid >> 5] = cm; redc1[tid >> 5] = cm1; }
    __syncthreads();

    if (tid == 0) {
        unsigned int tm = 0, tm1 = 0;
        #pragma unroll
        for (int w = 0; w < NWARP; w++) { tm += redc[w]; tm1 += redc1[w]; }
        // symmetric matrix + zero diagonal: matches = NN + 2*upper
        unsigned int matches_m  = (unsigned int)NN + 2u * tm;
        unsigned int matches_m1 = (unsigned int)NN + 2u * tm1;
        float ratio = (float)matches_m1 / (float)matches_m;   // matches_m >= NN > 0
        ratio = fmaxf(ratio, 1e-30f);
        g_ent[s] = -logf(ratio);

        // ---- fused finalize: last block computes the MSE ----
        __threadfence();
        unsigned int old = atomicAdd(&g_barrier, 1);
        if (old == 127u) {
            g_barrier = 0;            // reset for next graph replay
            __threadfence();          // make all g_ent writes visible
            float acc = 0.0f;
            #pragma unroll
            for (int i = 0; i < 64; i++) {
                float dp = __ldcg(&g_ent[i]);
                float dt = __ldcg(&g_ent[64 + i]);
                float dd = dp - dt;
                acc += dd * dd;
            }
            out[0] = acc * (1.0f / 64.0f);
        }
    }
}

extern "C" void kernel_launch(void* const* d_in, const int* in_sizes, int n_in,
                              void* d_out, int out_size) {
    const float* pred = (const float*)d_in[0];
    const float* tgt  = (const float*)d_in[1];
    float* out = (float*)d_out;
    sampen_kernel<<<128, NTHR>>>(pred, tgt, out);
}

// round 15
// speedup vs baseline: 1.1691x; 1.1691x over previous
#include <cuda_runtime.h>
#include <math.h>

#define T_LEN 1024
#define NN    1022            /* templates */
#define PAD   1104
#define RR    0.2f
#define NTHR  384
#define NWARP (NTHR / 32)

typedef unsigned long long u64;

__device__ float g_ent[128];
__device__ unsigned int g_barrier;

__device__ __forceinline__ u64 fma2(u64 a, u64 b, u64 c) {
    u64 r;
    asm("fma.rn.f32x2 %0, %1, %2, %3;" : "=l"(r) : "l"(a), "l"(b), "l"(c));
    return r;
}
__device__ __forceinline__ unsigned int lo32(u64 v) { return (unsigned int)v; }
__device__ __forceinline__ unsigned int hi32(u64 v) { return (unsigned int)(v >> 32); }

// Two pairs (lower k first): d2 = fma2(W,-1,A); u2 = fma2(d2,d2,-Rs2);
// insert both sign bits MSB-first.
#define FMA2SH(acc, W, A)                                            \
    do {                                                             \
        u64 _d = fma2((W), NEG1, (A));                               \
        u64 _u = fma2(_d, _d, NRS2);                                 \
        (acc) = __funnelshift_l(lo32(_u), (acc), 1);                 \
        (acc) = __funnelshift_l(hi32(_u), (acc), 1);                 \
    } while (0)

// ---- single self-contained unit (tail), software-pipelined loads ----
__device__ __forceinline__ void unit_count(const float* __restrict__ xs,
                                           const float* __restrict__ ys,
                                           int k0, int dbase, int remBase,
                                           float Rs2, u64 NEG1, u64 NRS2,
                                           unsigned int& cm, unsigned int& cm1) {
    const int B = k0 + dbase - 1;                     // ≡ 0 mod 4
    const ulonglong2* __restrict__ Ap = reinterpret_cast<const ulonglong2*>(xs + k0);
    const ulonglong2* __restrict__ Ep = reinterpret_cast<const ulonglong2*>(xs + B);
    const ulonglong2* __restrict__ Yp = reinterpret_cast<const ulonglong2*>(ys + B);
    unsigned int acc0 = 0, acc1 = 0, acc2 = 0, acc3 = 0;
    u64 e1 = Ep[0].y;
    ulonglong2 Y0 = Yp[0];
    // current-iteration operands (prefetched)
    ulonglong2 Ac = Ap[0];
    ulonglong2 Ec = Ep[1];
    ulonglong2 Yc = Yp[1];
    #pragma unroll
    for (int q = 0; q < 8; q++) {
        // prefetch next iteration (reads stay inside PAD; no guard needed)
        ulonglong2 An = Ap[q + 1];
        ulonglong2 En = Ep[q + 2];
        ulonglong2 Yn = Yp[q + 2];
        FMA2SH(acc0, Y0.x, Ac.x);  FMA2SH(acc0, Y0.y, Ac.y);   // s=0
        FMA2SH(acc1, e1,   Ac.x);  FMA2SH(acc1, Ec.x, Ac.y);   // s=1
        FMA2SH(acc2, Y0.y, Ac.x);  FMA2SH(acc2, Yc.x, Ac.y);   // s=2
        FMA2SH(acc3, Ec.x, Ac.x);  FMA2SH(acc3, Ec.y, Ac.y);   // s=3
        e1 = Ec.y; Y0 = Yc;
        Ac = An; Ec = En; Yc = Yn;
    }
    const float a32 = xs[k0 + 32];
    const float a33 = xs[k0 + 33];
    unsigned int acc[4] = {acc0, acc1, acc2, acc3};
    #pragma unroll
    for (int s = 0; s < 4; s++) {
        float W33 = xs[B + 33 + s];
        float W34 = xs[B + 34 + s];
        float d32 = a32 - W33;
        float d33 = a33 - W34;
        float u32 = fmaf(d32, d32, -Rs2);
        float u33 = fmaf(d33, d33, -Rs2);
        unsigned int ext = (__float_as_uint(u32) & 0x80000000u)
                         | ((__float_as_uint(u33) >> 1) & 0x40000000u);
        int rem = remBase - s;
        unsigned int mask = (rem >= 32) ? 0xffffffffu
                          : ((rem <= 0) ? 0u : (0xffffffffu << (32 - rem)));
        unsigned int S1 = __funnelshift_l(ext, acc[s], 1);
        unsigned int S2 = __funnelshift_l(ext, acc[s], 2);
        unsigned int mm = acc[s] & S1 & mask;
        cm  += __popc(mm);
        cm1 += __popc(mm & S2);
    }
}

// ---- two interleaved independent units (ILP x2), software-pipelined ----
__device__ __forceinline__ void unit2_count(const float* __restrict__ xs,
                                            const float* __restrict__ ys,
                                            int k0a, int dba, int remA,
                                            int k0b, int dbb, int remB,
                                            float Rs2, u64 NEG1, u64 NRS2,
                                            unsigned int& cm, unsigned int& cm1) {
    const int BA = k0a + dba - 1;
    const int BB = k0b + dbb - 1;
    const ulonglong2* __restrict__ ApA = reinterpret_cast<const ulonglong2*>(xs + k0a);
    const ulonglong2* __restrict__ EpA = reinterpret_cast<const ulonglong2*>(xs + BA);
    const ulonglong2* __restrict__ YpA = reinterpret_cast<const ulonglong2*>(ys + BA);
    const ulonglong2* __restrict__ ApB = reinterpret_cast<const ulonglong2*>(xs + k0b);
    const ulonglong2* __restrict__ EpB = reinterpret_cast<const ulonglong2*>(xs + BB);
    const ulonglong2* __restrict__ YpB = reinterpret_cast<const ulonglong2*>(ys + BB);
    unsigned int aA0 = 0, aA1 = 0, aA2 = 0, aA3 = 0;
    unsigned int aB0 = 0, aB1 = 0, aB2 = 0, aB3 = 0;
    u64 e1A = EpA[0].y;
    u64 e1B = EpB[0].y;
    ulonglong2 Y0A = YpA[0];
    ulonglong2 Y0B = YpB[0];
    // current-iteration operands (prefetched)
    ulonglong2 AcA = ApA[0], EcA = EpA[1], YcA = YpA[1];
    ulonglong2 AcB = ApB[0], EcB = EpB[1], YcB = YpB[1];
    #pragma unroll
    for (int q = 0; q < 8; q++) {
        // prefetch next iteration for BOTH streams before computing
        ulonglong2 AnA = ApA[q + 1];
        ulonglong2 EnA = EpA[q + 2];
        ulonglong2 YnA = YpA[q + 2];
        ulonglong2 AnB = ApB[q + 1];
        ulonglong2 EnB = EpB[q + 2];
        ulonglong2 YnB = YpB[q + 2];
        FMA2SH(aA0, Y0A.x, AcA.x);  FMA2SH(aB0, Y0B.x, AcB.x);
        FMA2SH(aA0, Y0A.y, AcA.y);  FMA2SH(aB0, Y0B.y, AcB.y);
        FMA2SH(aA1, e1A,   AcA.x);  FMA2SH(aB1, e1B,   AcB.x);
        FMA2SH(aA1, EcA.x, AcA.y);  FMA2SH(aB1, EcB.x, AcB.y);
        FMA2SH(aA2, Y0A.y, AcA.x);  FMA2SH(aB2, Y0B.y, AcB.x);
        FMA2SH(aA2, YcA.x, AcA.y);  FMA2SH(aB2, YcB.x, AcB.y);
        FMA2SH(aA3, EcA.x, AcA.x);  FMA2SH(aB3, EcB.x, AcB.x);
        FMA2SH(aA3, EcA.y, AcA.y);  FMA2SH(aB3, EcB.y, AcB.y);
        e1A = EcA.y; Y0A = YcA;
        e1B = EcB.y; Y0B = YcB;
        AcA = AnA; EcA = EnA; YcA = YnA;
        AcB = AnB; EcB = EnB; YcB = YnB;
    }
    {
        const float a32 = xs[k0a + 32];
        const float a33 = xs[k0a + 33];
        unsigned int acc[4] = {aA0, aA1, aA2, aA3};
        #pragma unroll
        for (int s = 0; s < 4; s++) {
            float W33 = xs[BA + 33 + s];
            float W34 = xs[BA + 34 + s];
            float d32 = a32 - W33;
            float d33 = a33 - W34;
            float u32 = fmaf(d32, d32, -Rs2);
            float u33 = fmaf(d33, d33, -Rs2);
            unsigned int ext = (__float_as_uint(u32) & 0x80000000u)
                             | ((__float_as_uint(u33) >> 1) & 0x40000000u);
            int rem = remA - s;
            unsigned int mask = (rem >= 32) ? 0xffffffffu
                              : ((rem <= 0) ? 0u : (0xffffffffu << (32 - rem)));
            unsigned int S1 = __funnelshift_l(ext, acc[s], 1);
            unsigned int S2 = __funnelshift_l(ext, acc[s], 2);
            unsigned int mm = acc[s] & S1 & mask;
            cm  += __popc(mm);
            cm1 += __popc(mm & S2);
        }
    }
    {
        const float a32 = xs[k0b + 32];
        const float a33 = xs[k0b + 33];
        unsigned int acc[4] = {aB0, aB1, aB2, aB3};
        #pragma unroll
        for (int s = 0; s < 4; s++) {
            float W33 = xs[BB + 33 + s];
            float W34 = xs[BB + 34 + s];
            float d32 = a32 - W33;
            float d33 = a33 - W34;
            float u32 = fmaf(d32, d32, -Rs2);
            float u33 = fmaf(d33, d33, -Rs2);
            unsigned int ext = (__float_as_uint(u32) & 0x80000000u)
                             | ((__float_as_uint(u33) >> 1) & 0x40000000u);
            int rem = remB - s;
            unsigned int mask = (rem >= 32) ? 0xffffffffu
                              : ((rem <= 0) ? 0u : (0xffffffffu << (32 - rem)));
            unsigned int S1 = __funnelshift_l(ext, acc[s], 1);
            unsigned int S2 = __funnelshift_l(ext, acc[s], 2);
            unsigned int mm = acc[s] & S1 & mask;
            cm  += __popc(mm);
            cm1 += __popc(mm & S2);
        }
    }
}

__global__ __launch_bounds__(NTHR, 1)
void sampen_kernel(const float* __restrict__ pred, const float* __restrict__ tgt,
                   float* __restrict__ out) {
    __shared__ __align__(16) float xs[PAD];
    __shared__ __align__(16) float ys[PAD];     // ys[i] = xs[i+1]
    __shared__ double redA[NWARP], redB[NWARP];
    __shared__ unsigned int redc[NWARP], redc1[NWARP];
    __shared__ float s_thresh2;

    const int s   = blockIdx.x;
    const int tid = threadIdx.x;
    const float* src = (s < 64) ? (pred + (size_t)s * T_LEN)
                                : (tgt  + (size_t)(s - 64) * T_LEN);

    // ---- load raw signal (3 strided loads for 384 threads) + zero pad ----
    float v0 = src[tid];
    float v1 = src[tid + NTHR];
    float v2 = (tid + 2 * NTHR < T_LEN) ? src[tid + 2 * NTHR] : 0.0f;
    xs[tid]        = v0;
    xs[tid + NTHR] = v1;
    if (tid + 2 * NTHR < T_LEN) xs[tid + 2 * NTHR] = v2;
    for (int i = T_LEN + tid; i < PAD; i += NTHR) xs[i] = 0.0f;

    // ---- std (ddof=1) in double; mean cancels inside |xi-xj|:
    //      squared scaled threshold Rs2 = (R*(std+eps))^2 ----
    double ls  = (double)v0 + (double)v1 + (double)v2;
    double ls2 = (double)v0 * (double)v0 + (double)v1 * (double)v1
               + (double)v2 * (double)v2;
    #pragma unroll
    for (int o = 16; o > 0; o >>= 1) {
        ls  += __shfl_down_sync(0xffffffffu, ls,  o);
        ls2 += __shfl_down_sync(0xffffffffu, ls2, o);
    }
    if ((tid & 31) == 0) { redA[tid >> 5] = ls; redB[tid >> 5] = ls2; }
    __syncthreads();
    // build shifted copy (xs fully visible now); overlaps with tid0's reduction
    for (int i = tid; i < PAD - 1; i += NTHR) ys[i] = xs[i + 1];
    if (tid == 0) {
        ys[PAD - 1] = 0.0f;
        double S = 0.0, S2 = 0.0;
        #pragma unroll
        for (int w = 0; w < NWARP; w++) { S += redA[w]; S2 += redB[w]; }
        double var = (S2 - S * S / (double)T_LEN) / (double)(T_LEN - 1);
        double sd  = sqrt(var);
        double rs  = (double)RR * (sd + 1e-8);
        s_thresh2  = (float)(rs * rs);
    }
    __syncthreads();
    const float Rs2 = s_thresh2;
    const u64 NEG1 = 0xBF800000BF800000ull;               // (-1.0f, -1.0f)
    const unsigned int nr = __float_as_uint(-Rs2);
    const u64 NRS2 = (u64)nr | ((u64)nr << 32);           // (-Rs2, -Rs2)

    // ---- upper-triangle counting: 4-diagonal groups, 2-unit ILP, 3 slots ----
    // Pair (P, 255-P): exactly 33 units. Thread (P = tid&127, sg = tid>>7 in [0,3))
    // owns 11 units: 5 x unit2 + 1 x unit1, identical trips for all warps.
    const int P  = tid & 127;
    const int sg = tid >> 7;           // warp-uniform, 0..2
    const int dA = 4 * P + 1;
    const int LA = NN - dA;            // 1021 - 4P
    const int dB = 1021 - 4 * P;       // partner group 255-P
    const int LB = NN - dB;            // 4P + 1
    const int CA = (LA + 31) >> 5;
    const int g0 = sg * 11;
    const int g1 = g0 + 11;

    unsigned int cm = 0, cm1 = 0;
    int j = g0;
    #pragma unroll 1
    for (; j + 1 < g1; j += 2) {
        bool inA0  = (j < CA);
        int dbase0 = inA0 ? dA : dB;
        int c0     = inA0 ? j  : j - CA;
        int Lb0    = inA0 ? LA : LB;
        int jb     = j + 1;
        bool inA1  = (jb < CA);
        int dbase1 = inA1 ? dA : dB;
        int c1     = inA1 ? jb : jb - CA;
        int Lb1    = inA1 ? LA : LB;
        unit2_count(xs, ys, c0 << 5, dbase0, Lb0 - (c0 << 5),
                            c1 << 5, dbase1, Lb1 - (c1 << 5),
                    Rs2, NEG1, NRS2, cm, cm1);
    }
    {   // 11th unit (all warps, uniform)
        bool inA  = (j < CA);
        int dbase = inA ? dA : dB;
        int c     = inA ? j  : j - CA;
        int Lb    = inA ? LA : LB;
        unit_count(xs, ys, c << 5, dbase, Lb - (c << 5), Rs2, NEG1, NRS2, cm, cm1);
    }

    // ---- reduce counts ----
    #pragma unroll
    for (int o = 16; o > 0; o >>= 1) {
        cm  += __shfl_down_sync(0xffffffffu, cm,  o);
        cm1 += __shfl_down_sync(0xffffffffu, cm1, o);
    }
    if ((tid & 31) == 0) { redc[tid >> 5] = cm; redc1[tid >> 5] = cm1; }
    __syncthreads();

    if (tid == 0) {
        unsigned int tm = 0, tm1 = 0;
        #pragma unroll
        for (int w = 0; w < NWARP; w++) { tm += redc[w]; tm1 += redc1[w]; }
        // symmetric matrix + zero diagonal: matches = NN + 2*upper
        unsigned int matches_m  = (unsigned int)NN + 2u * tm;
        unsigned int matches_m1 = (unsigned int)NN + 2u * tm1;
        float ratio = (float)matches_m1 / (float)matches_m;   // matches_m >= NN > 0
        ratio = fmaxf(ratio, 1e-30f);
        g_ent[s] = -logf(ratio);

        // ---- fused finalize: last block computes the MSE ----
        __threadfence();
        unsigned int old = atomicAdd(&g_barrier, 1);
        if (old == 127u) {
            g_barrier = 0;            // reset for next graph replay
            __threadfence();          // make all g_ent writes visible
            float acc = 0.0f;
            #pragma unroll
            for (int i = 0; i < 64; i++) {
                float dp = __ldcg(&g_ent[i]);
                float dt = __ldcg(&g_ent[64 + i]);
                float dd = dp - dt;
                acc += dd * dd;
            }
            out[0] = acc * (1.0f / 64.0f);
        }
    }
}

extern "C" void kernel_launch(void* const* d_in, const int* in_sizes, int n_in,
                              void* d_out, int out_size) {
    const float* pred = (const float*)d_in[0];
    const float* tgt  = (const float*)d_in[1];
    float* out = (float*)d_out;
    sampen_kernel<<<128, NTHR>>>(pred, tgt, out);
}